// round 15
// baseline (speedup 1.0000x reference)
#include <cuda_runtime.h>
#include <cuda_fp16.h>
#include <math.h>
#include <stdint.h>

#define D      128
#define B_MAX  4096
#define PCAP   (1 << 19)
#define PC     1536
#define NTILE  528           // 32*33/2 triangular 128x128 tiles
#define NCTA   296           // 2 per SM, all co-resident (grid == wave-1 capacity)
#define NPART  148           // k3 blocks / partials

// log2(e) folding constants
#define LOG2E   1.4426950408889634f
#define LN2     0.6931471805599453f
#define L2SQ    2.0813689810056077f      // log2e^2
#define CM2L2  (-4.1627379620112154f)    // -2*log2e^2

// ---------------- device scratch ----------------
__device__ __align__(16) __half g_h16[B_MAX * D];
__device__ float  g_mag[B_MAX];          // ||x||^2 * log2e^2 (scaled!)
__device__ float  g_nes[B_MAX];
__device__ int    g_lab[B_MAX];
__device__ double g_part[NPART];
__device__ int    g_pcnt;
__device__ int    g_tile;
__device__ int    g_done;
__device__ int    g_bar_cnt;
__device__ volatile int g_bar_gen;
__device__ int    g_pij[PCAP];
__device__ float  g_pd[PCAP];            // TRUE dist

// ---------------- helpers ----------------
__device__ __forceinline__ uint32_t smem_u32(const void* p) {
    uint32_t a;
    asm("{ .reg .u64 t; cvta.to.shared.u64 t, %1; cvt.u32.u64 %0, t; }" : "=r"(a) : "l"(p));
    return a;
}
__device__ __forceinline__ uint32_t h2_bits(__half2 h) {
    return *reinterpret_cast<uint32_t*>(&h);
}
__device__ __forceinline__ float fsqrt_fast(float x) {
    float r;
    asm("sqrt.approx.f32 %0, %1;" : "=f"(r) : "f"(x));
    return r;
}
__device__ __forceinline__ float ex2f(float x) {
    float r;
    asm("ex2.approx.f32 %0, %1;" : "=f"(r) : "f"(x));
    return r;
}
__device__ __forceinline__ void cpa16(uint32_t dst, const void* src) {
    asm volatile("cp.async.cg.shared.global [%0], [%1], 16;" :: "r"(dst), "l"(src));
}
#define CP_COMMIT() asm volatile("cp.async.commit_group;" ::: "memory")
#define CP_WAIT0()  asm volatile("cp.async.wait_group 0;" ::: "memory")
#define LDSM4(r, a)                                                                     \
    asm volatile("ldmatrix.sync.aligned.m8n8.x4.shared.b16 {%0,%1,%2,%3}, [%4];"        \
                 : "=r"((r)[0]), "=r"((r)[1]), "=r"((r)[2]), "=r"((r)[3]) : "r"(a))
#define MMA16816(c, a, b0, b1)                                                          \
    asm volatile("mma.sync.aligned.m16n8k16.row.col.f32.f16.f16.f32 "                   \
                 "{%0,%1,%2,%3}, {%4,%5,%6,%7}, {%8,%9}, {%0,%1,%2,%3};"                \
                 : "+f"((c)[0]), "+f"((c)[1]), "+f"((c)[2]), "+f"((c)[3])               \
                 : "r"((a)[0]), "r"((a)[1]), "r"((a)[2]), "r"((a)[3]),                  \
                   "r"(b0), "r"(b1))

__device__ __forceinline__ void tile_decode(int p, int& bx, int& by) {
    bx = (int)((sqrtf(8.0f * p + 1.0f) - 1.0f) * 0.5f);
    while ((bx + 1) * (bx + 2) / 2 <= p) bx++;
    while (bx * (bx + 1) / 2 > p) bx--;
    by = p - bx * (bx + 1) / 2;
}

// gen-based grid barrier (all NCTA CTAs co-resident)
__device__ __forceinline__ void grid_sync() {
    __syncthreads();
    if (threadIdx.x == 0) {
        __threadfence();
        int gen = g_bar_gen;
        if (atomicAdd(&g_bar_cnt, 1) == NCTA - 1) {
            g_bar_cnt = 0;
            __threadfence();
            g_bar_gen = gen + 1;
        } else {
            while (g_bar_gen == gen) { }
        }
        __threadfence();
    }
    __syncthreads();
}

// ---------------- smem layout ----------------
#define LDK   136
#define TILEB (128 * LDK * 2)
#define OFF_A    0
#define OFF_B    (OFF_A + TILEB)
#define OFF_LABA (OFF_B + TILEB)
#define OFF_MAGA (OFF_LABA + 1024)
#define OFF_LABB (OFF_MAGA + 1024)
#define OFF_MAGB (OFF_LABB + 1024)
#define OFF_CNT  (OFF_MAGB + 1024)
#define OFF_BASE (OFF_CNT + 4)
#define OFF_TN   (OFF_CNT + 8)
#define OFF_PIJ  (OFF_CNT + 16)
#define OFF_PD   (OFF_PIJ + PC * 4)
#define SMEM_SZ  (OFF_PD + PC * 4)

__device__ __forceinline__ void issue_tiles(uint32_t sb, int rb, int cb, int tid) {
    const char* ga = reinterpret_cast<const char*>(&g_h16[(size_t)rb * D]);
    const char* gb = reinterpret_cast<const char*>(&g_h16[(size_t)cb * D]);
#pragma unroll
    for (int it = 0; it < 8; it++) {
        int c = it * 256 + tid;
        int row = c >> 4, kc = c & 15;
        uint32_t dst = (uint32_t)(row * (LDK * 2) + kc * 16);
        uint32_t src = (uint32_t)(c * 16);
        cpa16(sb + OFF_A + dst, ga + src);
        cpa16(sb + OFF_B + dst, gb + src);
    }
}

// ---------------- k2: prep + persistent fp16 HMMA Gram --------------------
__global__ __launch_bounds__(256, 2) void k2_mma(const float* __restrict__ score,
                                                 const int* __restrict__ tw,
                                                 const float* __restrict__ alpha_p,
                                                 int B) {
    extern __shared__ char smem[];
    uint32_t sb = smem_u32(smem);
    int tid = threadIdx.x, wid = tid >> 5, lane = tid & 31;
    int warp_m = wid & 1, warp_n = wid >> 1;

    int* s_labA = reinterpret_cast<int*>(smem + OFF_LABA);
    float* s_magA = reinterpret_cast<float*>(smem + OFF_MAGA);
    int* s_labB = reinterpret_cast<int*>(smem + OFF_LABB);
    float* s_magB = reinterpret_cast<float*>(smem + OFF_MAGB);
    int* s_cnt = reinterpret_cast<int*>(smem + OFF_CNT);
    int* s_base = reinterpret_cast<int*>(smem + OFF_BASE);
    int* s_tn = reinterpret_cast<int*>(smem + OFF_TN);
    int* s_pij = reinterpret_cast<int*>(smem + OFF_PIJ);
    float* s_pd = reinterpret_cast<float*>(smem + OFF_PD);

    float alphaL = __ldg(alpha_p) * LOG2E;   // alpha * log2e

    // ===== phase 0: prep (fp16 convert, scaled mags, labels, resets) =====
    {
        __shared__ int s_any;
        if (tid == 0) s_any = 0;
        __syncthreads();
        // sampled dtype detection (256 samples/CTA): int32 labels (<64) all-zero
        // across samples has P=(1/64)^256 ~ 0; int64 guarantees zeros.
        int w = tw[2 * ((tid * 8) & (B / 2 - 1)) + 1];
        if (w) atomicOr(&s_any, 1);
        __syncthreads();
        int is64 = (s_any == 0);

        int gw = blockIdx.x * 8 + wid;        // 0..2367, stride 2368 over 4096 rows
        for (int row = gw; row < B; row += NCTA * 8) {
            float4 v = *reinterpret_cast<const float4*>(&score[(size_t)row * D + lane * 4]);
            uint32_t p0 = h2_bits(__floats2half2_rn(v.x, v.y));
            uint32_t p1 = h2_bits(__floats2half2_rn(v.z, v.w));
            *reinterpret_cast<uint2*>(&g_h16[(size_t)row * D + lane * 4]) = make_uint2(p0, p1);
            float s = v.x * v.x + v.y * v.y + v.z * v.z + v.w * v.w;
            s += __shfl_xor_sync(0xffffffffu, s, 16);
            s += __shfl_xor_sync(0xffffffffu, s, 8);
            s += __shfl_xor_sync(0xffffffffu, s, 4);
            s += __shfl_xor_sync(0xffffffffu, s, 2);
            s += __shfl_xor_sync(0xffffffffu, s, 1);
            if (lane == 0) {
                g_mag[row] = s * L2SQ;
                g_nes[row] = 0.0f;
                g_lab[row] = is64 ? tw[2 * row] : tw[row];
            }
        }
        if (blockIdx.x == 0 && tid == 0) { g_pcnt = 0; g_tile = 0; }
    }
    grid_sync();

    // ===== phase 1: persistent HMMA tile loop =====
    if (tid == 0) { *s_cnt = 0; *s_tn = atomicAdd(&g_tile, 1); }
    __syncthreads();
    int t = *s_tn;   // always < NTILE (296 < 528)

    int bx, by;
    tile_decode(t, bx, by);
    int rb = by * 128, cb = bx * 128;

    issue_tiles(sb, rb, cb, tid);
    CP_COMMIT();
    if (tid < 128) {
        s_labA[tid] = g_lab[rb + tid];
        s_magA[tid] = g_mag[rb + tid];
        s_labB[tid] = g_lab[cb + tid];
        s_magB[tid] = g_mag[cb + tid];
    }
    CP_WAIT0();
    __syncthreads();

    int buf = 0;
    const uint32_t a_base =
        ((uint32_t)(warp_m * 64 + (lane & 7) + ((lane >> 3) & 1) * 8) * LDK +
         (uint32_t)(lane >> 4) * 8) * 2;
    const uint32_t b_base =
        ((uint32_t)(warp_n * 32 + (lane & 15)) * LDK +
         (uint32_t)(lane >> 4) * 8) * 2;

    while (true) {
        if (tid == 0) *s_tn = atomicAdd(&g_tile, 1);   // visibility rides post-MMA sync

        // ---- MMA phase ----
        float acc[4][4][4];
#pragma unroll
        for (int ma = 0; ma < 4; ma++)
#pragma unroll
            for (int na = 0; na < 4; na++)
#pragma unroll
                for (int q = 0; q < 4; q++) acc[ma][na][q] = 0.0f;

        uint32_t sa = sb + OFF_A + a_base;
        uint32_t sB = sb + OFF_B + b_base;
#pragma unroll
        for (int ks = 0; ks < 8; ks++) {
            uint32_t ar[4][4], br[2][4];
#pragma unroll
            for (int ma = 0; ma < 4; ma++)
                LDSM4(ar[ma], sa + (uint32_t)(ma * 16 * LDK + ks * 16) * 2);
#pragma unroll
            for (int nb = 0; nb < 2; nb++)
                LDSM4(br[nb], sB + (uint32_t)(nb * 16 * LDK + ks * 16) * 2);
#pragma unroll
            for (int ma = 0; ma < 4; ma++)
#pragma unroll
                for (int na = 0; na < 4; na++)
                    MMA16816(acc[ma][na], ar[ma], br[na >> 1][na & 1], br[na >> 1][(na & 1) + 2]);
        }
        __syncthreads();

        // ---- prefetch next tile ----
        int tn = *s_tn;
        bool have_next = (tn < NTILE);
        int rbn = 0, cbn = 0;
        int nlabA = 0, nlabB = 0;
        float nmagA = 0.0f, nmagB = 0.0f;
        if (have_next) {
            int bxn, byn;
            tile_decode(tn, bxn, byn);
            rbn = byn * 128; cbn = bxn * 128;
            issue_tiles(sb, rbn, cbn, tid);
            CP_COMMIT();
            if (tid < 128) {
                nlabA = g_lab[rbn + tid];
                nmagA = g_mag[rbn + tid];
                nlabB = g_lab[cbn + tid];
                nmagB = g_mag[cbn + tid];
            }
        }

        // ---- epilogue (branchless negatives, log2e-folded) ----
        bool offdiag = (rb != cb);
        int ljv[8];
        float mjv[8];
#pragma unroll
        for (int na = 0; na < 4; na++)
#pragma unroll
            for (int q = 0; q < 2; q++) {
                int c = warp_n * 32 + na * 8 + (lane & 3) * 2 + q;
                ljv[na * 2 + q] = s_labB[buf * 128 + c];
                mjv[na * 2 + q] = s_magB[buf * 128 + c];
            }
        float csum[8];
#pragma unroll
        for (int q = 0; q < 8; q++) csum[q] = 0.0f;

#pragma unroll
        for (int ma = 0; ma < 4; ma++) {
#pragma unroll
            for (int h = 0; h < 2; h++) {
                int r = warp_m * 64 + ma * 16 + (lane >> 2) + h * 8;
                float mi = s_magA[buf * 128 + r];
                int li = s_labA[buf * 128 + r];
                float rs = 0.0f;
#pragma unroll
                for (int na = 0; na < 4; na++) {
#pragma unroll
                    for (int q = 0; q < 2; q++) {
                        int e = na * 2 + q;
                        float dot = acc[ma][na][h * 2 + q];
                        float d2 = fmaxf(fmaf(CM2L2, dot, mi + mjv[e]), 0.0f);
                        float dsc = fsqrt_fast(d2);          // dist * log2e
                        float ex = ex2f(alphaL - dsc);       // exp(alpha - dist)
                        bool pos = (li == ljv[e]);
                        float m = pos ? 0.0f : ex;
                        rs += m;
                        csum[e] += m;
                        if (pos) {                            // rare branch
                            int gi = rb + r;
                            int gj = cb + warp_n * 32 + na * 8 + (lane & 3) * 2 + q;
                            if (offdiag || gi < gj) {
                                int idx = atomicAdd(s_cnt, 1);
                                if (idx < PC) {
                                    s_pij[idx] = (gi << 12) | gj;
                                    s_pd[idx] = dsc * LN2;    // true dist
                                }
                            }
                        }
                    }
                }
                rs += __shfl_xor_sync(0xffffffffu, rs, 1);
                rs += __shfl_xor_sync(0xffffffffu, rs, 2);
                if ((lane & 3) == 0) atomicAdd(&g_nes[rb + r], rs);
            }
        }
        if (offdiag) {
#pragma unroll
            for (int na = 0; na < 4; na++)
#pragma unroll
                for (int q = 0; q < 2; q++) {
                    float v = csum[na * 2 + q];
                    v += __shfl_xor_sync(0xffffffffu, v, 4);
                    v += __shfl_xor_sync(0xffffffffu, v, 8);
                    v += __shfl_xor_sync(0xffffffffu, v, 16);
                    if (lane < 4)
                        atomicAdd(&g_nes[cb + warp_n * 32 + na * 8 + (lane & 3) * 2 + q], v);
                }
        }

        // ---- flush positive pairs ----
        __syncthreads();
        int npair = min(*s_cnt, PC);
        if (tid == 0) *s_base = atomicAdd(&g_pcnt, npair);
        __syncthreads();
        int base = *s_base;
        for (int q = tid; q < npair; q += 256) {
            if (base + q < PCAP) {
                g_pij[base + q] = s_pij[q];
                g_pd[base + q] = s_pd[q];
            }
        }
        if (tid == 0) *s_cnt = 0;

        if (!have_next) break;
        if (tid < 128) {
            s_labA[(buf ^ 1) * 128 + tid] = nlabA;
            s_magA[(buf ^ 1) * 128 + tid] = nmagA;
            s_labB[(buf ^ 1) * 128 + tid] = nlabB;
            s_magB[(buf ^ 1) * 128 + tid] = nmagB;
        }
        CP_WAIT0();
        __syncthreads();
        buf ^= 1;
        rb = rbn; cb = cbn;
    }
}

// ---------------- k3: pair terms + last-block final reduction -------------
__global__ __launch_bounds__(256) void k3_terms(float* __restrict__ out) {
    __shared__ double red[8];
    __shared__ int s_last;
    int tid = threadIdx.x;
    int n = min(g_pcnt, PCAP);
    double w = 0.0;
    for (int p = blockIdx.x * 256 + tid; p < n; p += NPART * 256) {
        int ij = g_pij[p];
        int i = ij >> 12, j = ij & 4095;
        float l = __logf(g_nes[i] + g_nes[j]) + g_pd[p];
        if (l > 0.0f) w += (double)l * (double)l;
    }
#pragma unroll
    for (int s = 16; s; s >>= 1) w += __shfl_xor_sync(0xffffffffu, w, s);
    int wd = tid >> 5;
    if ((tid & 31) == 0) red[wd] = w;
    __syncthreads();
    if (tid == 0) {
        double t = 0.0;
#pragma unroll
        for (int q = 0; q < 8; q++) t += red[q];
        g_part[blockIdx.x] = t;
        __threadfence();
        s_last = (atomicAdd(&g_done, 1) == NPART - 1);
    }
    __syncthreads();
    if (s_last) {
        double v = (tid < NPART) ? g_part[tid] : 0.0;
#pragma unroll
        for (int s = 16; s; s >>= 1) v += __shfl_xor_sync(0xffffffffu, v, s);
        if ((tid & 31) == 0) red[wd] = v;
        __syncthreads();
        if (tid == 0) {
            double t = 0.0;
#pragma unroll
            for (int q = 0; q < 8; q++) t += red[q];
            out[0] = (float)(t / (2.0 * (double)g_pcnt));
            g_done = 0;
        }
    }
}

// ---------------- launch ----------------
extern "C" void kernel_launch(void* const* d_in, const int* in_sizes, int n_in,
                              void* d_out, int out_size) {
    const float* score = (const float*)d_in[0];
    const int*   tgt   = (const int*)d_in[1];
    const float* alpha = (const float*)d_in[2];
    float* out = (float*)d_out;
    int B = in_sizes[1];  // 4096

    cudaFuncSetAttribute(k2_mma, cudaFuncAttributeMaxDynamicSharedMemorySize, SMEM_SZ);
    cudaFuncSetAttribute(k2_mma, cudaFuncAttributePreferredSharedMemoryCarveout, 100);

    k2_mma<<<NCTA, 256, SMEM_SZ>>>(score, tgt, alpha, B);
    k3_terms<<<NPART, 256>>>(out);
}

// round 16
// speedup vs baseline: 1.0652x; 1.0652x over previous
#include <cuda_runtime.h>
#include <cuda_fp16.h>
#include <math.h>
#include <stdint.h>

#define D      128
#define B_MAX  4096
#define PCAP   (1 << 19)
#define PCW    256           // per-warp positive-pair staging (expect ~30/warp/tile)
#define NTILE  528           // 32*33/2 triangular 128x128 tiles
#define NCTA   296           // 2 per SM, all co-resident
#define NPART  592           // k3 blocks

// log2(e) folding constants
#define LOG2E   1.4426950408889634f
#define LN2     0.6931471805599453f
#define L2SQ    2.0813689810056077f      // log2e^2
#define CM2L2  (-4.1627379620112154f)    // -2*log2e^2

// ---------------- device scratch ----------------
__device__ __align__(16) __half g_h16[B_MAX * D];
__device__ float  g_mag[B_MAX];          // ||x||^2 * log2e^2 (scaled)
__device__ float  g_nes[B_MAX];
__device__ int    g_lab[B_MAX];
__device__ double g_part[NPART];
__device__ int    g_pcnt;
__device__ int    g_tile;
__device__ int    g_done;
__device__ int    g_bar_cnt;
__device__ volatile int g_bar_gen;
__device__ int    g_pij[PCAP];
__device__ float  g_pd[PCAP];            // TRUE dist

// ---------------- helpers ----------------
__device__ __forceinline__ uint32_t smem_u32(const void* p) {
    uint32_t a;
    asm("{ .reg .u64 t; cvta.to.shared.u64 t, %1; cvt.u32.u64 %0, t; }" : "=r"(a) : "l"(p));
    return a;
}
__device__ __forceinline__ uint32_t h2_bits(__half2 h) {
    return *reinterpret_cast<uint32_t*>(&h);
}
__device__ __forceinline__ float fsqrt_fast(float x) {
    float r;
    asm("sqrt.approx.f32 %0, %1;" : "=f"(r) : "f"(x));
    return r;
}
__device__ __forceinline__ float ex2f(float x) {
    float r;
    asm("ex2.approx.f32 %0, %1;" : "=f"(r) : "f"(x));
    return r;
}
__device__ __forceinline__ void cpa16(uint32_t dst, const void* src) {
    asm volatile("cp.async.cg.shared.global [%0], [%1], 16;" :: "r"(dst), "l"(src));
}
#define CP_COMMIT() asm volatile("cp.async.commit_group;" ::: "memory")
#define CP_WAIT0()  asm volatile("cp.async.wait_group 0;" ::: "memory")
#define LDSM4(r, a)                                                                     \
    asm volatile("ldmatrix.sync.aligned.m8n8.x4.shared.b16 {%0,%1,%2,%3}, [%4];"        \
                 : "=r"((r)[0]), "=r"((r)[1]), "=r"((r)[2]), "=r"((r)[3]) : "r"(a))
#define MMA16816(c, a, b0, b1)                                                          \
    asm volatile("mma.sync.aligned.m16n8k16.row.col.f32.f16.f16.f32 "                   \
                 "{%0,%1,%2,%3}, {%4,%5,%6,%7}, {%8,%9}, {%0,%1,%2,%3};"                \
                 : "+f"((c)[0]), "+f"((c)[1]), "+f"((c)[2]), "+f"((c)[3])               \
                 : "r"((a)[0]), "r"((a)[1]), "r"((a)[2]), "r"((a)[3]),                  \
                   "r"(b0), "r"(b1))

__device__ __forceinline__ void tile_decode(int p, int& bx, int& by) {
    bx = (int)((sqrtf(8.0f * p + 1.0f) - 1.0f) * 0.5f);
    while ((bx + 1) * (bx + 2) / 2 <= p) bx++;
    while (bx * (bx + 1) / 2 > p) bx--;
    by = p - bx * (bx + 1) / 2;
}

// gen-based grid barrier (all NCTA CTAs co-resident)
__device__ __forceinline__ void grid_sync() {
    __syncthreads();
    if (threadIdx.x == 0) {
        __threadfence();
        int gen = g_bar_gen;
        if (atomicAdd(&g_bar_cnt, 1) == NCTA - 1) {
            g_bar_cnt = 0;
            __threadfence();
            g_bar_gen = gen + 1;
        } else {
            while (g_bar_gen == gen) { }
        }
        __threadfence();
    }
    __syncthreads();
}

// ---------------- smem layout ----------------
#define LDK   136
#define TILEB (128 * LDK * 2)            // 34816 B
#define OFF_A    0
#define OFF_B    (OFF_A + TILEB)
#define OFF_LABA (OFF_B + TILEB)         // [2][128] int
#define OFF_MAGA (OFF_LABA + 1024)
#define OFF_LABB (OFF_MAGA + 1024)
#define OFF_MAGB (OFF_LABB + 1024)
#define OFF_TN   (OFF_MAGB + 1024)
#define OFF_WCNT (OFF_TN + 16)           // [8] int
#define OFF_WPIJ (OFF_WCNT + 32)         // [8][PCW] int
#define OFF_WPD  (OFF_WPIJ + 8 * PCW * 4)
#define SMEM_SZ  (OFF_WPD + 8 * PCW * 4)

__device__ __forceinline__ void issue_tiles(uint32_t sb, int rb, int cb, int tid) {
    const char* ga = reinterpret_cast<const char*>(&g_h16[(size_t)rb * D]);
    const char* gb = reinterpret_cast<const char*>(&g_h16[(size_t)cb * D]);
#pragma unroll
    for (int it = 0; it < 8; it++) {
        int c = it * 256 + tid;
        int row = c >> 4, kc = c & 15;
        uint32_t dst = (uint32_t)(row * (LDK * 2) + kc * 16);
        uint32_t src = (uint32_t)(c * 16);
        cpa16(sb + OFF_A + dst, ga + src);
        cpa16(sb + OFF_B + dst, gb + src);
    }
}

// ---------------- k2: prep + persistent fp16 HMMA Gram --------------------
__global__ __launch_bounds__(256, 2) void k2_mma(const float* __restrict__ score,
                                                 const int* __restrict__ tw,
                                                 const float* __restrict__ alpha_p,
                                                 int B) {
    extern __shared__ char smem[];
    uint32_t sb = smem_u32(smem);
    int tid = threadIdx.x, wid = tid >> 5, lane = tid & 31;
    int warp_m = wid & 1, warp_n = wid >> 1;

    int* s_labA = reinterpret_cast<int*>(smem + OFF_LABA);
    float* s_magA = reinterpret_cast<float*>(smem + OFF_MAGA);
    int* s_labB = reinterpret_cast<int*>(smem + OFF_LABB);
    float* s_magB = reinterpret_cast<float*>(smem + OFF_MAGB);
    int* s_tn = reinterpret_cast<int*>(smem + OFF_TN);
    int* s_wcnt = reinterpret_cast<int*>(smem + OFF_WCNT);
    int* s_wpij = reinterpret_cast<int*>(smem + OFF_WPIJ);
    float* s_wpd = reinterpret_cast<float*>(smem + OFF_WPD);

    float alphaL = __ldg(alpha_p) * LOG2E;

    // ===== phase 0: prep =====
    {
        __shared__ int s_any;
        if (tid == 0) s_any = 0;
        __syncthreads();
        int w = tw[2 * ((tid * 8) & (B / 2 - 1)) + 1];
        if (w) atomicOr(&s_any, 1);
        __syncthreads();
        int is64 = (s_any == 0);

        int gw = blockIdx.x * 8 + wid;
        for (int row = gw; row < B; row += NCTA * 8) {
            float4 v = *reinterpret_cast<const float4*>(&score[(size_t)row * D + lane * 4]);
            uint32_t p0 = h2_bits(__floats2half2_rn(v.x, v.y));
            uint32_t p1 = h2_bits(__floats2half2_rn(v.z, v.w));
            *reinterpret_cast<uint2*>(&g_h16[(size_t)row * D + lane * 4]) = make_uint2(p0, p1);
            float s = v.x * v.x + v.y * v.y + v.z * v.z + v.w * v.w;
            s += __shfl_xor_sync(0xffffffffu, s, 16);
            s += __shfl_xor_sync(0xffffffffu, s, 8);
            s += __shfl_xor_sync(0xffffffffu, s, 4);
            s += __shfl_xor_sync(0xffffffffu, s, 2);
            s += __shfl_xor_sync(0xffffffffu, s, 1);
            if (lane == 0) {
                g_mag[row] = s * L2SQ;
                g_nes[row] = 0.0f;
                g_lab[row] = is64 ? tw[2 * row] : tw[row];
            }
        }
        if (blockIdx.x == 0 && tid == 0) { g_pcnt = 0; g_tile = 0; }
    }
    grid_sync();

    // ===== phase 1: persistent HMMA tile loop =====
    if (tid == 0) *s_tn = atomicAdd(&g_tile, 1);
    if (tid < 8) s_wcnt[tid] = 0;
    __syncthreads();
    int t = *s_tn;   // always < NTILE (296 < 528)

    int bx, by;
    tile_decode(t, bx, by);
    int rb = by * 128, cb = bx * 128;

    issue_tiles(sb, rb, cb, tid);
    CP_COMMIT();
    if (tid < 128) {
        s_labA[tid] = g_lab[rb + tid];
        s_magA[tid] = g_mag[rb + tid];
        s_labB[tid] = g_lab[cb + tid];
        s_magB[tid] = g_mag[cb + tid];
    }
    CP_WAIT0();
    __syncthreads();

    int buf = 0;
    const uint32_t a_base =
        ((uint32_t)(warp_m * 64 + (lane & 7) + ((lane >> 3) & 1) * 8) * LDK +
         (uint32_t)(lane >> 4) * 8) * 2;
    const uint32_t b_base =
        ((uint32_t)(warp_n * 32 + (lane & 15)) * LDK +
         (uint32_t)(lane >> 4) * 8) * 2;

    while (true) {
        if (tid == 0) *s_tn = atomicAdd(&g_tile, 1);   // visibility rides post-MMA sync

        // ---- MMA phase ----
        float acc[4][4][4];
#pragma unroll
        for (int ma = 0; ma < 4; ma++)
#pragma unroll
            for (int na = 0; na < 4; na++)
#pragma unroll
                for (int q = 0; q < 4; q++) acc[ma][na][q] = 0.0f;

        uint32_t sa = sb + OFF_A + a_base;
        uint32_t sB = sb + OFF_B + b_base;
#pragma unroll
        for (int ks = 0; ks < 8; ks++) {
            uint32_t ar[4][4], br[2][4];
#pragma unroll
            for (int ma = 0; ma < 4; ma++)
                LDSM4(ar[ma], sa + (uint32_t)(ma * 16 * LDK + ks * 16) * 2);
#pragma unroll
            for (int nb = 0; nb < 2; nb++)
                LDSM4(br[nb], sB + (uint32_t)(nb * 16 * LDK + ks * 16) * 2);
#pragma unroll
            for (int ma = 0; ma < 4; ma++)
#pragma unroll
                for (int na = 0; na < 4; na++)
                    MMA16816(acc[ma][na], ar[ma], br[na >> 1][na & 1], br[na >> 1][(na & 1) + 2]);
        }
        __syncthreads();   // A/B smem dead; *s_tn visible

        // ---- prefetch next tile ----
        int tn = *s_tn;
        bool have_next = (tn < NTILE);
        int rbn = 0, cbn = 0;
        int nlabA = 0, nlabB = 0;
        float nmagA = 0.0f, nmagB = 0.0f;
        if (have_next) {
            int bxn, byn;
            tile_decode(tn, bxn, byn);
            rbn = byn * 128; cbn = bxn * 128;
            issue_tiles(sb, rbn, cbn, tid);
            CP_COMMIT();
            if (tid < 128) {
                nlabA = g_lab[rbn + tid];
                nmagA = g_mag[rbn + tid];
                nlabB = g_lab[cbn + tid];
                nmagB = g_mag[cbn + tid];
            }
        }

        // ---- epilogue (branchless negatives; warp-private positive staging) ----
        bool offdiag = (rb != cb);
        int ljv[8];
        float mjv[8];
#pragma unroll
        for (int na = 0; na < 4; na++)
#pragma unroll
            for (int q = 0; q < 2; q++) {
                int c = warp_n * 32 + na * 8 + (lane & 3) * 2 + q;
                ljv[na * 2 + q] = s_labB[buf * 128 + c];
                mjv[na * 2 + q] = s_magB[buf * 128 + c];
            }
        float csum[8];
#pragma unroll
        for (int q = 0; q < 8; q++) csum[q] = 0.0f;

#pragma unroll
        for (int ma = 0; ma < 4; ma++) {
#pragma unroll
            for (int h = 0; h < 2; h++) {
                int r = warp_m * 64 + ma * 16 + (lane >> 2) + h * 8;
                float mi = s_magA[buf * 128 + r];
                int li = s_labA[buf * 128 + r];
                float rs = 0.0f;
#pragma unroll
                for (int na = 0; na < 4; na++) {
#pragma unroll
                    for (int q = 0; q < 2; q++) {
                        int e = na * 2 + q;
                        float dot = acc[ma][na][h * 2 + q];
                        float d2 = fmaxf(fmaf(CM2L2, dot, mi + mjv[e]), 0.0f);
                        float dsc = fsqrt_fast(d2);          // dist * log2e
                        float ex = ex2f(alphaL - dsc);       // exp(alpha - dist)
                        bool pos = (li == ljv[e]);
                        float m = pos ? 0.0f : ex;
                        rs += m;
                        csum[e] += m;
                        if (pos) {                            // rare branch
                            int gi = rb + r;
                            int gj = cb + warp_n * 32 + na * 8 + (lane & 3) * 2 + q;
                            if (offdiag || gi < gj) {
                                int idx = atomicAdd(&s_wcnt[wid], 1);
                                if (idx < PCW) {
                                    s_wpij[wid * PCW + idx] = (gi << 12) | gj;
                                    s_wpd[wid * PCW + idx] = dsc * LN2;
                                }
                            }
                        }
                    }
                }
                rs += __shfl_xor_sync(0xffffffffu, rs, 1);
                rs += __shfl_xor_sync(0xffffffffu, rs, 2);
                if ((lane & 3) == 0) atomicAdd(&g_nes[rb + r], rs);
            }
        }
        if (offdiag) {
#pragma unroll
            for (int na = 0; na < 4; na++)
#pragma unroll
                for (int q = 0; q < 2; q++) {
                    float v = csum[na * 2 + q];
                    v += __shfl_xor_sync(0xffffffffu, v, 4);
                    v += __shfl_xor_sync(0xffffffffu, v, 8);
                    v += __shfl_xor_sync(0xffffffffu, v, 16);
                    if (lane < 4)
                        atomicAdd(&g_nes[cb + warp_n * 32 + na * 8 + (lane & 3) * 2 + q], v);
                }
        }

        // ---- warp-synchronous positive-pair flush (no CTA barrier) ----
        __syncwarp();
        {
            int cnt = min(s_wcnt[wid], PCW);
            int basep = 0;
            if (lane == 0 && cnt) basep = atomicAdd(&g_pcnt, cnt);
            basep = __shfl_sync(0xffffffffu, basep, 0);
            for (int q2 = lane; q2 < cnt; q2 += 32) {
                int o = basep + q2;
                if (o < PCAP) {
                    g_pij[o] = s_wpij[wid * PCW + q2];
                    g_pd[o] = s_wpd[wid * PCW + q2];
                }
            }
            if (lane == 0) s_wcnt[wid] = 0;
        }
        __syncwarp();

        if (!have_next) break;
        if (tid < 128) {
            s_labA[(buf ^ 1) * 128 + tid] = nlabA;
            s_magA[(buf ^ 1) * 128 + tid] = nmagA;
            s_labB[(buf ^ 1) * 128 + tid] = nlabB;
            s_magB[(buf ^ 1) * 128 + tid] = nmagB;
        }
        CP_WAIT0();
        __syncthreads();
        buf ^= 1;
        rb = rbn; cb = cbn;
    }
}

// ---------------- k3: pair terms, pipelined gathers + last-block reduce ----
__global__ __launch_bounds__(128) void k3_terms(float* __restrict__ out) {
    __shared__ double red[4];
    __shared__ int s_last;
    int tid = threadIdx.x;
    int n = min(g_pcnt, PCAP);
    const int stride = NPART * 128;
    int pA = blockIdx.x * 128 + tid;
    int pB = pA + stride;

    // batched front loads (MLP=4)
    bool vA = pA < n, vB = pB < n;
    int ijA = 0, ijB = 0;
    float pdA = 0.0f, pdB = 0.0f;
    if (vA) { ijA = g_pij[pA]; pdA = g_pd[pA]; }
    if (vB) { ijB = g_pij[pB]; pdB = g_pd[pB]; }
    float nsA = 0.0f, nsB = 0.0f;
    if (vA) nsA = g_nes[ijA >> 12] + g_nes[ijA & 4095];
    if (vB) nsB = g_nes[ijB >> 12] + g_nes[ijB & 4095];

    double w = 0.0;
    if (vA) {
        float l = __logf(nsA) + pdA;
        if (l > 0.0f) w += (double)l * (double)l;
    }
    if (vB) {
        float l = __logf(nsB) + pdB;
        if (l > 0.0f) w += (double)l * (double)l;
    }
    // tail (normally empty: n < 2*stride)
    for (int p = pA + 2 * stride; p < n; p += stride) {
        int ij = g_pij[p];
        float l = __logf(g_nes[ij >> 12] + g_nes[ij & 4095]) + g_pd[p];
        if (l > 0.0f) w += (double)l * (double)l;
    }

#pragma unroll
    for (int s = 16; s; s >>= 1) w += __shfl_xor_sync(0xffffffffu, w, s);
    int wd = tid >> 5;
    if ((tid & 31) == 0) red[wd] = w;
    __syncthreads();
    if (tid == 0) {
        double t = red[0] + red[1] + red[2] + red[3];
        g_part[blockIdx.x] = t;
        __threadfence();
        s_last = (atomicAdd(&g_done, 1) == NPART - 1);
    }
    __syncthreads();
    if (s_last) {
        double v = 0.0;
        for (int q = tid; q < NPART; q += 128) v += g_part[q];
#pragma unroll
        for (int s = 16; s; s >>= 1) v += __shfl_xor_sync(0xffffffffu, v, s);
        if ((tid & 31) == 0) red[wd] = v;
        __syncthreads();
        if (tid == 0) {
            double t = red[0] + red[1] + red[2] + red[3];
            out[0] = (float)(t / (2.0 * (double)g_pcnt));
            g_done = 0;
        }
    }
}

// ---------------- launch ----------------
extern "C" void kernel_launch(void* const* d_in, const int* in_sizes, int n_in,
                              void* d_out, int out_size) {
    const float* score = (const float*)d_in[0];
    const int*   tgt   = (const int*)d_in[1];
    const float* alpha = (const float*)d_in[2];
    float* out = (float*)d_out;
    int B = in_sizes[1];  // 4096

    cudaFuncSetAttribute(k2_mma, cudaFuncAttributeMaxDynamicSharedMemorySize, SMEM_SZ);
    cudaFuncSetAttribute(k2_mma, cudaFuncAttributePreferredSharedMemoryCarveout, 100);

    k2_mma<<<NCTA, 256, SMEM_SZ>>>(score, tgt, alpha, B);
    k3_terms<<<NPART, 128>>>(out);
}